// round 3
// baseline (speedup 1.0000x reference)
#include <cuda_runtime.h>
#include <cstdint>

// Problem constants: B=512, T=2048, I=4, H=100, O=1
#define NBATCH   4      // batches per block
#define HDIM     100
#define PADH     104    // padded H (multiple of 8, keeps 16B alignment, pad stays 0)
#define TLEN     2048
#define MAIN_T   416    // 4 groups * 104 lane slots (warps 0..12)
#define BLOCK_T  448    // + 32 reducer threads (warp 13)
#define NBLOCKS  128    // 512 / 4

// ---- packed fp32x2 ops (Blackwell FFMA2 path, only reachable via PTX) ----
__device__ __forceinline__ unsigned long long ffma2(unsigned long long a,
                                                    unsigned long long b,
                                                    unsigned long long c) {
    unsigned long long d;
    asm("fma.rn.f32x2 %0, %1, %2, %3;" : "=l"(d) : "l"(a), "l"(b), "l"(c));
    return d;
}
__device__ __forceinline__ unsigned long long fmul2(unsigned long long a,
                                                    unsigned long long b) {
    unsigned long long d;
    asm("mul.rn.f32x2 %0, %1, %2;" : "=l"(d) : "l"(a), "l"(b));
    return d;
}
__device__ __forceinline__ unsigned long long fadd2(unsigned long long a,
                                                    unsigned long long b) {
    unsigned long long d;
    asm("add.rn.f32x2 %0, %1, %2;" : "=l"(d) : "l"(a), "l"(b));
    return d;
}
__device__ __forceinline__ float hsum2(unsigned long long a) {
    unsigned int lo, hi;
    asm("mov.b64 {%0, %1}, %2;" : "=r"(lo), "=r"(hi) : "l"(a));
    return __uint_as_float(lo) + __uint_as_float(hi);
}

// tanh(x) = 1 - 2/(exp(2x)+1): 2 MUFU + ~3 fma-class ops, ~1e-7 abs error.
__device__ __forceinline__ float fast_tanh(float x) {
    float e = __expf(x + x);
    return 1.0f - __fdividef(2.0f, e + 1.0f);
}

__global__ void __launch_bounds__(BLOCK_T, 1)
crnn_kernel(const float* __restrict__ x,      // [512, 2048, 4]
            const float* __restrict__ W_ih,   // [100, 4]
            const float* __restrict__ W_hh,   // [100, 100]
            const float* __restrict__ W_fc,   // [1, 100]
            const float* __restrict__ b_fc,   // [1]
            float* __restrict__ out)          // [512, 2048, 1]
{
    // double-buffered hidden state, one row per local batch, padded to 104
    __shared__ __align__(16) float hbuf[2][NBATCH][PADH];

    const int tid   = threadIdx.x;
    const int bbase = blockIdx.x * NBATCH;

    // zero both buffers (pad region must stay exactly 0 forever: reducers
    // read it with zero weights, so it must not contain NaN garbage)
    for (int i = tid; i < 2 * NBATCH * PADH; i += BLOCK_T)
        ((float*)hbuf)[i] = 0.0f;

    if (tid < MAIN_T) {
        // ---------------- main threads: one (batch, h) recurrence lane ----
        const int b_loc = tid / PADH;          // 0..3
        const int hh    = tid - b_loc * PADH;  // 0..103 (>=100 are idle lanes)
        const int row   = (hh < HDIM) ? hh : (HDIM - 1);  // clamp for safe loads
        const int bg    = bbase + b_loc;

        // W_hh row -> 100 regs as 50 fp32x2 pairs (pairs over K)
        unsigned long long w[50];
        const ulonglong2* wrow =
            reinterpret_cast<const ulonglong2*>(W_hh + row * HDIM);
        #pragma unroll
        for (int j = 0; j < 25; j++) {
            ulonglong2 v = wrow[j];
            w[2 * j]     = v.x;
            w[2 * j + 1] = v.y;
        }

        // W_ih row (4 floats) as two fp32x2 pairs
        const ulonglong2 wihv =
            *reinterpret_cast<const ulonglong2*>(W_ih + row * 4);

        // x[b] rows: float4 per timestep, 16B aligned
        const ulonglong2* xp =
            reinterpret_cast<const ulonglong2*>(x) + (size_t)bg * TLEN;

        __syncthreads();                       // barrier #0 (init done)

        ulonglong2 xcur = xp[0];

        #pragma unroll 1
        for (int t = 0; t < TLEN; t++) {
            // prefetch next timestep's x (latency hidden under the dot product)
            const int tn = (t < TLEN - 1) ? (t + 1) : t;
            ulonglong2 xnext = xp[tn];

            const int cur = t & 1;

            // accumulator init = input projection xp_t (natural fp32x2 pairs)
            unsigned long long a0 = fmul2(xcur.x, wihv.x);
            a0 = ffma2(xcur.y, wihv.y, a0);
            unsigned long long a1 = 0ull, a2 = 0ull, a3 = 0ull;

            // K-vectorized matvec: 25x LDS.128 (broadcast) + 50x FFMA2
            const ulonglong2* hb =
                reinterpret_cast<const ulonglong2*>(&hbuf[cur][b_loc][0]);
            #pragma unroll
            for (int j = 0; j < 25; j++) {
                ulonglong2 h4 = hb[j];
                if (j & 1) {
                    a2 = ffma2(h4.x, w[2 * j], a2);
                    a3 = ffma2(h4.y, w[2 * j + 1], a3);
                } else {
                    a0 = ffma2(h4.x, w[2 * j], a0);
                    a1 = ffma2(h4.y, w[2 * j + 1], a1);
                }
            }

            const float pre  = hsum2(fadd2(fadd2(a0, a1), fadd2(a2, a3)));
            const float hnew = fast_tanh(pre);

            if (hh < HDIM)
                hbuf[cur ^ 1][b_loc][hh] = hnew;

            xcur = xnext;
            __syncthreads();                   // barrier #(t+1)
        }
    } else {
        // ---------------- reducer warp (warp 13): output projection -------
        // lane r: batch b_loc = r/8, phase q = r%8; strided K so the
        // LDS pattern is bank-conflict-free (8*b + q covers all 32 banks).
        const int r     = tid - MAIN_T;        // 0..31
        const int b_loc = r >> 3;
        const int q     = r & 7;

        float wv[13];
        #pragma unroll
        for (int j = 0; j < 13; j++) {
            const int k = q + 8 * j;
            wv[j] = (k < HDIM) ? W_fc[k] : 0.0f;
        }
        const float bias = b_fc[0];
        float* op = out + (size_t)(bbase + b_loc) * TLEN;

        __syncthreads();                       // barrier #0

        #pragma unroll 1
        for (int t = 0; t < TLEN; t++) {
            __syncthreads();                   // barrier #(t+1): h_t is ready
            const int nxt = (t & 1) ^ 1;       // buffer mains just wrote
            float s = 0.0f;
            #pragma unroll
            for (int j = 0; j < 13; j++)
                s = fmaf(hbuf[nxt][b_loc][q + 8 * j], wv[j], s);
            // sum the 8 phases of this batch (aligned 8-lane segments)
            s += __shfl_xor_sync(0xFFFFFFFFu, s, 1);
            s += __shfl_xor_sync(0xFFFFFFFFu, s, 2);
            s += __shfl_xor_sync(0xFFFFFFFFu, s, 4);
            if (q == 0)
                op[t] = s + bias;
        }
    }
}

extern "C" void kernel_launch(void* const* d_in, const int* in_sizes, int n_in,
                              void* d_out, int out_size) {
    const float* x    = (const float*)d_in[0];  // [512,2048,4]
    const float* W_ih = (const float*)d_in[1];  // [100,4]
    const float* W_hh = (const float*)d_in[2];  // [100,100]
    const float* W_fc = (const float*)d_in[3];  // [1,100]
    const float* b_fc = (const float*)d_in[4];  // [1]
    float* out = (float*)d_out;                 // [512,2048,1]

    crnn_kernel<<<NBLOCKS, BLOCK_T>>>(x, W_ih, W_hh, W_fc, b_fc, out);
}